// round 1
// baseline (speedup 1.0000x reference)
#include <cuda_runtime.h>

// MedianFilter: xs [B=4,T=32,N=128,D=32] f32, A [1,128,128] i32.
// Per (b,t,n,d): lower median over {xs[b,t-1,n,d] if t>0, xs[b,t+1,n,d] if t<T-1,
//                                  xs[b,t,j,d] for j in nonzero(A[0][n]+I)}.
// Exact selection via MSB-first 4-bit radix-select on orderable uint keys.

#define Bc 4
#define Tc 32
#define Nc 128
#define Dc 32

__device__ __forceinline__ unsigned f2u(float f) {
    unsigned s = __float_as_uint(f);
    return s ^ ((unsigned)((int)s >> 31) | 0x80000000u);
}
__device__ __forceinline__ float u2f(unsigned u) {
    unsigned s = (u & 0x80000000u) ? (u ^ 0x80000000u) : ~u;
    return __uint_as_float(s);
}

__global__ __launch_bounds__(1024, 1)
void median_kernel(const float* __restrict__ xs,
                   const int* __restrict__ A,
                   float* __restrict__ out)
{
    __shared__ unsigned tile[Nc * Dc];        // transformed current frame, 16KB
    __shared__ unsigned char nbr[Nc * Nc];    // compacted neighbor lists, 16KB
    __shared__ int cnt[Nc];

    const int bt   = blockIdx.x;        // 0..B*T-1
    const int t    = bt & (Tc - 1);
    const int tid  = threadIdx.x;
    const int lane = tid & 31;
    const int w    = tid >> 5;

    const float* cur = xs + (size_t)bt * (Nc * Dc);

    // Load + transform current-frame tile (all 1024 threads)
    #pragma unroll
    for (int i = tid; i < Nc * Dc; i += 1024)
        tile[i] = f2u(cur[i]);

    // Compact adjacency row -> neighbor index list (threads 0..127, one node each).
    // Candidate j iff A[n][j] != 0 or j == n (A + I).
    if (tid < Nc) {
        const int* row = A + tid * Nc;
        int c = 0;
        #pragma unroll 4
        for (int j = 0; j < Nc; j++) {
            if (row[j] != 0 || j == tid) {
                nbr[tid * Nc + c] = (unsigned char)j;
                c++;
            }
        }
        cnt[tid] = c;
    }
    __syncthreads();

    const bool hasPrev = (t > 0);
    const bool hasNext = (t < Tc - 1);
    const float* prevp = xs + (size_t)(bt - 1) * (Nc * Dc);
    const float* nextp = xs + (size_t)(bt + 1) * (Nc * Dc);

    // One warp per node; 32 warps cover 128 nodes in 4 iterations.
    for (int n = w; n < Nc; n += 32) {
        const int k = cnt[n];
        const int ktot = k + (hasPrev ? 1 : 0) + (hasNext ? 1 : 0);
        unsigned m = (unsigned)((ktot - 1) >> 1);   // lower-median rank

        const unsigned prevU = hasPrev ? f2u(prevp[n * Dc + lane]) : 0u;
        const unsigned nextU = hasNext ? f2u(nextp[n * Dc + lane]) : 0u;

        unsigned prefix = 0u;
        unsigned result = 0u;
        bool done = false;
        const unsigned char* lst = &nbr[n * Nc];

        #pragma unroll 1
        for (int p = 0; p < 8; p++) {
            if (__all_sync(0xFFFFFFFFu, done)) break;
            const int shift = 28 - 4 * p;

            unsigned long long h0 = 0ull, h1 = 0ull;

            // histogram update for one candidate key u
            #define PROC(u_)                                                      \
            {                                                                     \
                unsigned u__ = (u_);                                              \
                bool match = ((((u__ ^ prefix) >> shift) >> 4) == 0u) && !done;   \
                unsigned nib = (u__ >> shift) & 15u;                              \
                unsigned long long inc =                                          \
                    match ? (1ull << ((nib & 7u) * 8u)) : 0ull;                   \
                if (nib & 8u) h1 += inc; else h0 += inc;                          \
            }

            for (int i = 0; i < k; i++) {
                unsigned u = tile[((int)lst[i]) * Dc + lane];
                PROC(u);
            }
            if (hasPrev) PROC(prevU);
            if (hasNext) PROC(nextU);

            // pick the nibble bin containing rank m
            bool needRes = false;
            if (!done) {
                unsigned mm = m;
                int g = -1;
                unsigned rem = 0;
                #pragma unroll
                for (int nb = 0; nb < 16; nb++) {
                    unsigned c =
                        (unsigned)(((nb < 8 ? h0 : h1) >> ((nb & 7) * 8)) & 0xFFull);
                    if (g < 0) {
                        if (mm < c) { g = nb; rem = c; }
                        else        { mm -= c; }
                    }
                }
                m = mm;
                prefix |= ((unsigned)g) << shift;
                needRes = (rem == 1u);      // unique survivor -> fetch it directly
            }

            if (__any_sync(0xFFFFFFFFu, needRes)) {
                for (int i = 0; i < k; i++) {
                    unsigned u = tile[((int)lst[i]) * Dc + lane];
                    if (needRes && (((u ^ prefix) >> shift) == 0u)) result = u;
                }
                if (hasPrev && needRes && (((prevU ^ prefix) >> shift) == 0u)) result = prevU;
                if (hasNext && needRes && (((nextU ^ prefix) >> shift) == 0u)) result = nextU;
                if (needRes) done = true;
            }
            #undef PROC
        }

        // Lanes not resolved early: all 32 bits of prefix are determined
        // (remaining survivors are duplicates equal to prefix).
        float r = u2f(done ? result : prefix);
        out[(size_t)bt * (Nc * Dc) + n * Dc + lane] = r;
    }
}

extern "C" void kernel_launch(void* const* d_in, const int* in_sizes, int n_in,
                              void* d_out, int out_size)
{
    const float* xs = (const float*)d_in[0];
    const int*   A  = (const int*)d_in[1];
    float*       out = (float*)d_out;
    (void)in_sizes; (void)n_in; (void)out_size;

    median_kernel<<<Bc * Tc, 1024>>>(xs, A, out);
}

// round 2
// speedup vs baseline: 2.5591x; 2.5591x over previous
#include <cuda_runtime.h>

// MedianFilter: xs [B=4,T=32,N=128,D=32] f32, A [1,128,128] i32.
// Per (b,t,n,d): lower median over {prev-self (t>0), next-self (t<T-1),
//   xs[b,t,j,d] for j with (A+I)[n][j]!=0}.
// Exact MSB-first 4-bit radix-select on orderable uint keys, with survivor
// compaction into a per-thread shared buffer after each pass.

#define Bc 4
#define Tc 32
#define Nc 128
#define Dc 32
#define NT 1024
#define SLOTS 48

extern __shared__ unsigned g_buf[];   // SLOTS * NT words = 192KB

__device__ __forceinline__ unsigned f2u(float f) {
    unsigned s = __float_as_uint(f);
    return s ^ ((unsigned)((int)s >> 31) | 0x80000000u);
}
__device__ __forceinline__ float u2f(unsigned u) {
    unsigned s = (u & 0x80000000u) ? (u ^ 0x80000000u) : ~u;
    return __uint_as_float(s);
}

// Select the nibble bin containing rank m from byte-packed histograms
// h0 (bins 0-7) / h1 (bins 8-15). Counts <= 130 so byte prefix sums don't
// overflow. Updates m to the rank within the bin, sets rem = bin count.
__device__ __forceinline__ int select_bin(unsigned long long h0,
                                          unsigned long long h1,
                                          unsigned &m, unsigned &rem)
{
    unsigned long long s0 = h0 * 0x0101010101010101ull;
    unsigned total0 = (unsigned)(s0 >> 56);
    unsigned long long S, H;
    int base;
    unsigned mm = m;
    if (mm < total0) { S = s0; H = h0; base = 0; }
    else {
        mm -= total0;
        S = h1 * 0x0101010101010101ull; H = h1; base = 8;
    }
    // smallest g with cum[g] > mm (branchless binary search over 8 bytes)
    int g = 0;
    if ((unsigned)((S >> 24) & 0xFF) <= mm) g = 4;
    if ((unsigned)((S >> (8 * (g + 1))) & 0xFF) <= mm) g += 2;
    if ((unsigned)((S >> (8 * g)) & 0xFF) <= mm) g += 1;
    unsigned before = g ? (unsigned)((S >> (8 * (g - 1))) & 0xFF) : 0u;
    rem = (unsigned)((H >> (8 * g)) & 0xFF);
    m = mm - before;
    return base + g;
}

#define HIST(u_)                                                    \
    {                                                               \
        unsigned nib_ = ((u_) >> shift) & 15u;                      \
        unsigned long long inc_ = 1ull << ((nib_ & 7u) * 8u);       \
        if (nib_ & 8u) h1 += inc_; else h0 += inc_;                 \
    }

#define HISTF(u_)                                                   \
    {                                                               \
        unsigned u__ = (u_);                                        \
        bool match_ = (((u__ ^ prefix) >> shift) >> 4) == 0u;       \
        unsigned nib_ = (u__ >> shift) & 15u;                       \
        unsigned long long inc_ =                                   \
            match_ ? (1ull << ((nib_ & 7u) * 8u)) : 0ull;           \
        if (nib_ & 8u) h1 += inc_; else h0 += inc_;                 \
    }

__global__ __launch_bounds__(NT, 1)
void median_kernel(const float* __restrict__ xs,
                   const int* __restrict__ A,
                   float* __restrict__ out)
{
    __shared__ unsigned tile[Nc * Dc];       // 16KB
    __shared__ unsigned char nbr[Nc * Nc];   // 16KB
    __shared__ short cnt[Nc];

    const int bt   = blockIdx.x;
    const int t    = bt & (Tc - 1);
    const int tid  = threadIdx.x;
    const int lane = tid & 31;
    const int w    = tid >> 5;

    const float* cur = xs + (size_t)bt * (Nc * Dc);
    for (int i = tid; i < Nc * Dc; i += NT) tile[i] = f2u(cur[i]);

    if (tid < Nc) {
        const int* row = A + tid * Nc;
        int c = 0;
        #pragma unroll 4
        for (int j = 0; j < Nc; j++)
            if (row[j] != 0 || j == tid) nbr[tid * Nc + (c++)] = (unsigned char)j;
        cnt[tid] = (short)c;
    }
    __syncthreads();

    const bool hasPrev = (t > 0);
    const bool hasNext = (t < Tc - 1);
    const float* prevp = xs + (size_t)(bt - 1) * (Nc * Dc);
    const float* nextp = xs + (size_t)(bt + 1) * (Nc * Dc);

    for (int n = w; n < Nc; n += 32) {
        const int k = cnt[n];
        const unsigned char* lst = &nbr[n * Nc];
        const int ktot = k + (int)hasPrev + (int)hasNext;
        unsigned m = (unsigned)((ktot - 1) >> 1);

        const unsigned prevU = hasPrev ? f2u(prevp[n * Dc + lane]) : 0u;
        const unsigned nextU = hasNext ? f2u(nextp[n * Dc + lane]) : 0u;

        unsigned prefix = 0, result = 0, rem = 0;
        int c = -1;          // -1 = not compacted yet
        bool done = false;

        // ---------- pass 0 (shift = 28): no prefix filter ----------
        {
            const int shift = 28;
            unsigned long long h0 = 0ull, h1 = 0ull;
            for (int i = 0; i < k; i++) {
                unsigned u = tile[(((int)lst[i]) << 5) | lane];
                HIST(u);
            }
            if (hasPrev) HIST(prevU);
            if (hasNext) HIST(nextU);

            int g = select_bin(h0, h1, m, rem);
            prefix = (unsigned)g << shift;

            if (rem <= SLOTS) {
                int c2 = 0;
                for (int i = 0; i < k; i++) {
                    unsigned u = tile[(((int)lst[i]) << 5) | lane];
                    if ((u >> shift) == (unsigned)g) { g_buf[c2 * NT + tid] = u; c2++; }
                }
                if (hasPrev && (prevU >> shift) == (unsigned)g) { g_buf[c2 * NT + tid] = prevU; c2++; }
                if (hasNext && (nextU >> shift) == (unsigned)g) { g_buf[c2 * NT + tid] = nextU; c2++; }
                c = c2;
                if (c == 1) { result = g_buf[tid]; done = true; }
            }
        }

        // ---------- passes 1..7 ----------
        #pragma unroll 1
        for (int p = 1; p < 8; p++) {
            if (__all_sync(0xFFFFFFFFu, done)) break;
            const int shift = 28 - 4 * p;

            if (!done) {
                unsigned long long h0 = 0ull, h1 = 0ull;
                if (c < 0) {
                    // rare fallback: filtered full scan
                    for (int i = 0; i < k; i++) {
                        unsigned u = tile[(((int)lst[i]) << 5) | lane];
                        HISTF(u);
                    }
                    if (hasPrev) HISTF(prevU);
                    if (hasNext) HISTF(nextU);
                } else {
                    for (int i = 0; i < c; i++) {
                        unsigned u = g_buf[i * NT + tid];
                        HIST(u);
                    }
                }

                int g = select_bin(h0, h1, m, rem);
                prefix |= (unsigned)g << shift;

                if (c < 0) {
                    if (rem <= SLOTS) {
                        int c2 = 0;
                        for (int i = 0; i < k; i++) {
                            unsigned u = tile[(((int)lst[i]) << 5) | lane];
                            if (((u ^ prefix) >> shift) == 0u) { g_buf[c2 * NT + tid] = u; c2++; }
                        }
                        if (hasPrev && ((prevU ^ prefix) >> shift) == 0u) { g_buf[c2 * NT + tid] = prevU; c2++; }
                        if (hasNext && ((nextU ^ prefix) >> shift) == 0u) { g_buf[c2 * NT + tid] = nextU; c2++; }
                        c = c2;
                    }
                } else if (rem < (unsigned)c) {
                    // in-place compaction (read index >= write index)
                    int c2 = 0;
                    for (int i = 0; i < c; i++) {
                        unsigned u = g_buf[i * NT + tid];
                        if (((u >> shift) & 15u) == (unsigned)g) { g_buf[c2 * NT + tid] = u; c2++; }
                    }
                    c = c2;
                }
                if (c == 1) { result = g_buf[tid]; done = true; }
            }
        }

        // Unresolved lanes: every nibble was selected -> survivors are
        // duplicates equal to the full prefix.
        float r = u2f(done ? result : prefix);
        out[(size_t)bt * (Nc * Dc) + n * Dc + lane] = r;
    }
}

extern "C" void kernel_launch(void* const* d_in, const int* in_sizes, int n_in,
                              void* d_out, int out_size)
{
    const float* xs  = (const float*)d_in[0];
    const int*   A   = (const int*)d_in[1];
    float*       out = (float*)d_out;
    (void)in_sizes; (void)n_in; (void)out_size;

    cudaFuncSetAttribute(median_kernel,
                         cudaFuncAttributeMaxDynamicSharedMemorySize,
                         SLOTS * NT * 4);
    median_kernel<<<Bc * Tc, NT, SLOTS * NT * 4>>>(xs, A, out);
}